// round 2
// baseline (speedup 1.0000x reference)
#include <cuda_runtime.h>
#include <math.h>

#define N_NODES 50000
#define N_EDGES 800000
#define F 128
#define BN_EPS 1e-5f
#define RRELU_SLOPE 0.2291666666666667f  // (1/8 + 1/3)/2 = 11/48

// ---------------- scratch (device globals: no allocation allowed) ----------------
__device__ float g_agg[2][(size_t)N_NODES * F];   // agg1, agg2
__device__ float g_h[(size_t)N_NODES * F];        // hidden activations
__device__ float g_WT[4 * F * F];                 // k-major transposed weights:
                                                  // [0]=W1_rel [1]=W1_root [2]=W2_rel [3]=W2_root
__device__ float g_colsum[F];
__device__ float g_colsq[F];
__device__ float g_scale[F];
__device__ float g_shift[F];

// ---------------- init: zero agg1 + stats accumulators ----------------
__global__ void k_init() {
    size_t i = (size_t)blockIdx.x * blockDim.x + threadIdx.x;
    size_t total = (size_t)N_NODES * F / 4;
    float4 z = make_float4(0.f, 0.f, 0.f, 0.f);
    float4* a = reinterpret_cast<float4*>(&g_agg[0][0]);
    for (size_t j = i; j < total; j += (size_t)gridDim.x * blockDim.x)
        a[j] = z;
    if (i < F) { g_colsum[i] = 0.f; g_colsq[i] = 0.f; }
}

// ---------------- transpose weights to k-major (WT[k*F+o] = W[o*F+k]) ----------------
__global__ void k_transpose(const float* __restrict__ W1rel, const float* __restrict__ W1root,
                            const float* __restrict__ W2rel, const float* __restrict__ W2root) {
    int i = blockIdx.x * blockDim.x + threadIdx.x;   // grid exactly covers 4*F*F
    int m = i / (F * F);
    int r = i % (F * F);
    int k = r / F, o = r % F;
    const float* W = (m == 0) ? W1rel : (m == 1) ? W1root : (m == 2) ? W2rel : W2root;
    g_WT[i] = W[o * F + k];
}

// ---------------- scatter: agg[tgt] += w_e * feat[src]  (warp per edge) ----------------
__global__ void k_scatter(int layer, const float* __restrict__ x,
                          const int* __restrict__ ei, const float* __restrict__ ew) {
    unsigned gid = blockIdx.x * blockDim.x + threadIdx.x;
    int e = gid >> 5;
    int lane = gid & 31;
    if (e >= N_EDGES) return;
    const float* feat = layer ? g_h : x;
    float* agg = &g_agg[layer][0];

    int s = __ldg(&ei[e]);              // edge_index[0][e] = src
    int t = __ldg(&ei[N_EDGES + e]);    // edge_index[1][e] = tgt
    float w = __ldg(&ew[e]);

    float4 v = *reinterpret_cast<const float4*>(feat + (size_t)s * F + lane * 4);
    float4 r = make_float4(v.x * w, v.y * w, v.z * w, v.w * w);
    float* dst = agg + (size_t)t * F + lane * 4;
    asm volatile("red.global.add.v4.f32 [%0], {%1,%2,%3,%4};"
                 :: "l"(dst), "f"(r.x), "f"(r.y), "f"(r.z), "f"(r.w) : "memory");
}

// ---------------- fused GEMM: C = agg @ Wrel^T + A1 @ Wroot^T + bias ----------------
// Treated as K=256 GEMM: k<128 reads agg/WTrel, k>=128 reads A1/WTroot (contiguous in g_WT).
// 128x128 block tile, 256 threads, 8x8 microtile, k-tile 8.
__global__ void __launch_bounds__(256, 2)
k_gemm(int layer, const float* __restrict__ x, const float* __restrict__ bias,
       float* __restrict__ out) {
    __shared__ float Asm[8][132];   // [kk][row], padded to avoid store conflicts
    __shared__ float Wsm[8][128];   // [kk][o]

    const float* A0 = &g_agg[layer][0];
    const float* A1 = layer ? g_h : x;
    const float* WT = &g_WT[layer * 2 * F * F];
    float* C = layer ? out : g_h;

    int tid = threadIdx.x;
    int tx = tid & 15;        // col group (8 cols each)
    int ty = tid >> 4;        // row group (8 rows each)
    int row0 = blockIdx.x * 128;

    int arow = tid >> 1;            // 0..127: A-tile row this thread loads
    int apair = (tid & 1) * 4;      // 0 or 4: which half of the 8 k's

    float acc[8][8];
#pragma unroll
    for (int r = 0; r < 8; r++)
#pragma unroll
        for (int c = 0; c < 8; c++) acc[r][c] = 0.f;

    for (int kb = 0; kb < 256; kb += 8) {
        const float* A = (kb < 128) ? A0 : A1;
        int ak = kb & 127;

        // load A tile fragment (float4) and W tile fragment (float4) into regs
        float4 av = make_float4(0.f, 0.f, 0.f, 0.f);
        int grow = row0 + arow;
        if (grow < N_NODES)
            av = *reinterpret_cast<const float4*>(A + (size_t)grow * F + ak + apair);
        float4 wv = *reinterpret_cast<const float4*>(WT + (size_t)kb * F + tid * 4);

        __syncthreads();   // previous iteration's smem reads done
        Asm[apair + 0][arow] = av.x;
        Asm[apair + 1][arow] = av.y;
        Asm[apair + 2][arow] = av.z;
        Asm[apair + 3][arow] = av.w;
        *reinterpret_cast<float4*>(&Wsm[0][0] + tid * 4) = wv;
        __syncthreads();

#pragma unroll
        for (int kk = 0; kk < 8; kk++) {
            float ar[8], wr[8];
            *reinterpret_cast<float4*>(ar)     = *reinterpret_cast<const float4*>(&Asm[kk][ty * 8]);
            *reinterpret_cast<float4*>(ar + 4) = *reinterpret_cast<const float4*>(&Asm[kk][ty * 8 + 4]);
            *reinterpret_cast<float4*>(wr)     = *reinterpret_cast<const float4*>(&Wsm[kk][tx * 8]);
            *reinterpret_cast<float4*>(wr + 4) = *reinterpret_cast<const float4*>(&Wsm[kk][tx * 8 + 4]);
#pragma unroll
            for (int r = 0; r < 8; r++)
#pragma unroll
                for (int c = 0; c < 8; c++)
                    acc[r][c] += ar[r] * wr[c];
        }
    }

    // epilogue: + bias, store
    float b[8];
#pragma unroll
    for (int c = 0; c < 8; c++) b[c] = __ldg(&bias[tx * 8 + c]);

#pragma unroll
    for (int r = 0; r < 8; r++) {
        int grow = row0 + ty * 8 + r;
        if (grow < N_NODES) {
            float* crow = C + (size_t)grow * F + tx * 8;
            float4 o0 = make_float4(acc[r][0] + b[0], acc[r][1] + b[1],
                                    acc[r][2] + b[2], acc[r][3] + b[3]);
            float4 o1 = make_float4(acc[r][4] + b[4], acc[r][5] + b[5],
                                    acc[r][6] + b[6], acc[r][7] + b[7]);
            *reinterpret_cast<float4*>(crow) = o0;
            *reinterpret_cast<float4*>(crow + 4) = o1;
        }
    }
}

// ---------------- per-channel sums for BN ----------------
__global__ void k_stats() {
    __shared__ float s_sum[8][128];
    __shared__ float s_sq[8][128];
    int lane = threadIdx.x & 31;
    int w = threadIdx.x >> 5;
    float4 sum = make_float4(0.f, 0.f, 0.f, 0.f);
    float4 sq  = make_float4(0.f, 0.f, 0.f, 0.f);
    for (int r = blockIdx.x * 8 + w; r < N_NODES; r += gridDim.x * 8) {
        float4 v = *reinterpret_cast<const float4*>(g_h + (size_t)r * F + lane * 4);
        sum.x += v.x; sum.y += v.y; sum.z += v.z; sum.w += v.w;
        sq.x += v.x * v.x; sq.y += v.y * v.y; sq.z += v.z * v.z; sq.w += v.w * v.w;
    }
    *reinterpret_cast<float4*>(&s_sum[w][lane * 4]) = sum;
    *reinterpret_cast<float4*>(&s_sq[w][lane * 4])  = sq;
    __syncthreads();
    if (w < 4) {
        int c = w * 32 + lane;
        float ts = 0.f, tq = 0.f;
#pragma unroll
        for (int i = 0; i < 8; i++) { ts += s_sum[i][c]; tq += s_sq[i][c]; }
        atomicAdd(&g_colsum[c], ts);
        atomicAdd(&g_colsq[c], tq);
    }
}

// ---------------- fold mean/var into scale/shift ----------------
__global__ void k_meanvar(const float* __restrict__ gamma, const float* __restrict__ beta) {
    int c = threadIdx.x;
    float mean = g_colsum[c] / (float)N_NODES;
    float var = g_colsq[c] / (float)N_NODES - mean * mean;
    float sc = gamma[c] * rsqrtf(var + BN_EPS);
    g_scale[c] = sc;
    g_shift[c] = beta[c] - mean * sc;
}

// ---------------- BN apply + RReLU in place; also zero agg2 ----------------
__global__ void k_bnrelu() {
    size_t total = (size_t)N_NODES * F / 4;
    float4* h4 = reinterpret_cast<float4*>(g_h);
    float4* a2 = reinterpret_cast<float4*>(&g_agg[1][0]);
    float4 z = make_float4(0.f, 0.f, 0.f, 0.f);
    for (size_t i = (size_t)blockIdx.x * blockDim.x + threadIdx.x; i < total;
         i += (size_t)gridDim.x * blockDim.x) {
        int cb = ((int)(i & 31)) * 4;   // F/4 = 32 float4 per row
        float4 v = h4[i];
        v.x = v.x * g_scale[cb + 0] + g_shift[cb + 0];
        v.y = v.y * g_scale[cb + 1] + g_shift[cb + 1];
        v.z = v.z * g_scale[cb + 2] + g_shift[cb + 2];
        v.w = v.w * g_scale[cb + 3] + g_shift[cb + 3];
        v.x = v.x >= 0.f ? v.x : v.x * RRELU_SLOPE;
        v.y = v.y >= 0.f ? v.y : v.y * RRELU_SLOPE;
        v.z = v.z >= 0.f ? v.z : v.z * RRELU_SLOPE;
        v.w = v.w >= 0.f ? v.w : v.w * RRELU_SLOPE;
        h4[i] = v;
        a2[i] = z;
    }
}

// ---------------- launch ----------------
extern "C" void kernel_launch(void* const* d_in, const int* in_sizes, int n_in,
                              void* d_out, int out_size) {
    const float* x      = (const float*)d_in[0];
    const int*   ei     = (const int*)d_in[1];
    const float* ew     = (const float*)d_in[2];
    const float* W1rel  = (const float*)d_in[3];
    const float* b1     = (const float*)d_in[4];
    const float* W1root = (const float*)d_in[5];
    const float* gamma  = (const float*)d_in[6];
    const float* beta   = (const float*)d_in[7];
    const float* W2rel  = (const float*)d_in[8];
    const float* b2     = (const float*)d_in[9];
    const float* W2root = (const float*)d_in[10];
    float* out = (float*)d_out;

    const int GEMM_BLOCKS = (N_NODES + 127) / 128;          // 391
    const int SCAT_BLOCKS = (N_EDGES * 32 + 255) / 256;     // 100000

    k_init<<<1024, 256>>>();
    k_transpose<<<(4 * F * F) / 256, 256>>>(W1rel, W1root, W2rel, W2root);
    k_scatter<<<SCAT_BLOCKS, 256>>>(0, x, ei, ew);
    k_gemm<<<GEMM_BLOCKS, 256>>>(0, x, b1, out);            // writes g_h
    k_stats<<<128, 256>>>();
    k_meanvar<<<1, 128>>>(gamma, beta);
    k_bnrelu<<<2048, 256>>>();                              // also zeros agg2
    k_scatter<<<SCAT_BLOCKS, 256>>>(1, x, ei, ew);
    k_gemm<<<GEMM_BLOCKS, 256>>>(1, x, b2, out);            // writes d_out
}

// round 9
// speedup vs baseline: 1.6623x; 1.6623x over previous
#include <cuda_runtime.h>
#include <math.h>
#include <cstdint>

#define N_NODES 50000
#define N_EDGES 800000
#define F 128
#define BN_EPS 1e-5f
#define RRELU_SLOPE 0.2291666666666667f  // (1/8 + 1/3)/2 = 11/48

// ---------------- scratch (device globals: no allocation allowed) ----------------
__device__ float g_agg[2][(size_t)N_NODES * F];   // agg1, agg2
__device__ float g_h[(size_t)N_NODES * F];        // hidden activations
__device__ float g_colsum[F];
__device__ float g_colsq[F];
__device__ float g_scale[F];
__device__ float g_shift[F];

__device__ __forceinline__ uint32_t cvt_tf32(float f) {
    uint32_t u;
    asm("cvt.rna.tf32.f32 %0, %1;" : "=r"(u) : "f"(f));
    return u;
}

// ---------------- init: zero agg1 + stats accumulators ----------------
__global__ void k_init() {
    size_t i = (size_t)blockIdx.x * blockDim.x + threadIdx.x;
    size_t total = (size_t)N_NODES * F / 4;
    float4 z = make_float4(0.f, 0.f, 0.f, 0.f);
    float4* a = reinterpret_cast<float4*>(&g_agg[0][0]);
    for (size_t j = i; j < total; j += (size_t)gridDim.x * blockDim.x) a[j] = z;
    if (i < F) { g_colsum[i] = 0.f; g_colsq[i] = 0.f; }
}

// ---------------- scatter: agg[tgt] += w_e * feat[src]  (warp per edge) ----------------
__global__ void k_scatter(int layer, const float* __restrict__ x,
                          const int* __restrict__ ei, const float* __restrict__ ew) {
    unsigned gid = blockIdx.x * blockDim.x + threadIdx.x;
    int e = gid >> 5;
    int lane = gid & 31;
    if (e >= N_EDGES) return;
    const float* feat = layer ? g_h : x;
    float* agg = &g_agg[layer][0];

    int s = __ldg(&ei[e]);
    int t = __ldg(&ei[N_EDGES + e]);
    float w = __ldg(&ew[e]);

    float4 v = *reinterpret_cast<const float4*>(feat + (size_t)s * F + lane * 4);
    float4 r = make_float4(v.x * w, v.y * w, v.z * w, v.w * w);
    float* dst = agg + (size_t)t * F + lane * 4;
    asm volatile("red.global.add.v4.f32 [%0], {%1,%2,%3,%4};"
                 :: "l"(dst), "f"(r.x), "f"(r.y), "f"(r.z), "f"(r.w) : "memory");
}

// ---------------- mma.sync tf32 fused GEMM: C = agg@Wrel^T + A1@Wroot^T + bias ----------
// Block: 128 rows x 128 out-cols, 256 threads (8 warps), warp tile 64x32 (4x4 m16n8k8).
// K = 256 total, streamed as 8 k-tiles of 32: tiles 0..3 = (agg, Wrel), 4..7 = (A1, Wroot).
// Smem: A[128][36], B[128][36] words (tf32 bits), stride 36 -> conflict-free fragments.
__global__ void __launch_bounds__(256, 2)
k_gemm_mma(int layer, const float* __restrict__ x,
           const float* __restrict__ Wrel, const float* __restrict__ Wroot,
           const float* __restrict__ bias, float* __restrict__ out) {
    __shared__ uint32_t As[128][36];
    __shared__ uint32_t Bs[128][36];

    const float* A0 = &g_agg[layer][0];
    const float* A1 = layer ? g_h : x;
    float* C = layer ? out : g_h;

    int tid = threadIdx.x;
    int lane = tid & 31, wid = tid >> 5;
    int row0 = blockIdx.x * 128;
    int mbase = (wid & 1) * 64;     // warp M offset
    int nbase = (wid >> 1) * 32;    // warp N offset
    int grp = lane >> 2;            // 0..7
    int tig = lane & 3;             // 0..3

    float acc[4][4][4];             // [mt][nt][c0..c3]
#pragma unroll
    for (int mt = 0; mt < 4; mt++)
#pragma unroll
        for (int nt = 0; nt < 4; nt++)
#pragma unroll
            for (int q = 0; q < 4; q++) acc[mt][nt][q] = 0.f;

#pragma unroll 1
    for (int t = 0; t < 8; t++) {
        const float* Asrc = (t < 4) ? A0 : A1;
        const float* Bsrc = (t < 4) ? Wrel : Wroot;
        int koff = (t & 3) * 32;

        // stage A tile: 128 rows x 32 k = 1024 float4, 4 per thread
#pragma unroll
        for (int j = 0; j < 4; j++) {
            int i = tid + j * 256;
            int r = i >> 3;                 // 8 float4 per row
            int k4 = (i & 7) << 2;
            float4 v = make_float4(0.f, 0.f, 0.f, 0.f);
            if (row0 + r < N_NODES)
                v = *reinterpret_cast<const float4*>(Asrc + (size_t)(row0 + r) * F + koff + k4);
            uint4 u = make_uint4(cvt_tf32(v.x), cvt_tf32(v.y), cvt_tf32(v.z), cvt_tf32(v.w));
            *reinterpret_cast<uint4*>(&As[r][k4]) = u;
        }
        // stage B tile: W[n][k] row-major consumed directly
#pragma unroll
        for (int j = 0; j < 4; j++) {
            int i = tid + j * 256;
            int r = i >> 3;
            int k4 = (i & 7) << 2;
            float4 v = *reinterpret_cast<const float4*>(Bsrc + (size_t)r * F + koff + k4);
            uint4 u = make_uint4(cvt_tf32(v.x), cvt_tf32(v.y), cvt_tf32(v.z), cvt_tf32(v.w));
            *reinterpret_cast<uint4*>(&Bs[r][k4]) = u;
        }
        __syncthreads();

#pragma unroll
        for (int ks = 0; ks < 4; ks++) {
            int k0 = ks * 8;
            uint32_t a[4][4], b[4][2];
#pragma unroll
            for (int mt = 0; mt < 4; mt++) {
                int r = mbase + mt * 16 + grp;
                a[mt][0] = As[r][k0 + tig];
                a[mt][1] = As[r + 8][k0 + tig];
                a[mt][2] = As[r][k0 + tig + 4];
                a[mt][3] = As[r + 8][k0 + tig + 4];
            }
#pragma unroll
            for (int nt = 0; nt < 4; nt++) {
                int n = nbase + nt * 8 + grp;
                b[nt][0] = Bs[n][k0 + tig];
                b[nt][1] = Bs[n][k0 + tig + 4];
            }
#pragma unroll
            for (int mt = 0; mt < 4; mt++)
#pragma unroll
                for (int nt = 0; nt < 4; nt++)
                    asm volatile(
                        "mma.sync.aligned.m16n8k8.row.col.f32.tf32.tf32.f32 "
                        "{%0,%1,%2,%3}, {%4,%5,%6,%7}, {%8,%9}, {%0,%1,%2,%3};"
                        : "+f"(acc[mt][nt][0]), "+f"(acc[mt][nt][1]),
                          "+f"(acc[mt][nt][2]), "+f"(acc[mt][nt][3])
                        : "r"(a[mt][0]), "r"(a[mt][1]), "r"(a[mt][2]), "r"(a[mt][3]),
                          "r"(b[nt][0]), "r"(b[nt][1]));
        }
        __syncthreads();
    }

    // epilogue: + bias, store. c0/c1 = row grp, cols 2*tig, 2*tig+1; c2/c3 = row grp+8.
#pragma unroll
    for (int nt = 0; nt < 4; nt++) {
        int c = nbase + nt * 8 + tig * 2;
        float b0 = __ldg(&bias[c]);
        float b1 = __ldg(&bias[c + 1]);
#pragma unroll
        for (int mt = 0; mt < 4; mt++) {
            int r0 = row0 + mbase + mt * 16 + grp;
            int r1 = r0 + 8;
            if (r0 < N_NODES) {
                float2 o = make_float2(acc[mt][nt][0] + b0, acc[mt][nt][1] + b1);
                *reinterpret_cast<float2*>(C + (size_t)r0 * F + c) = o;
            }
            if (r1 < N_NODES) {
                float2 o = make_float2(acc[mt][nt][2] + b0, acc[mt][nt][3] + b1);
                *reinterpret_cast<float2*>(C + (size_t)r1 * F + c) = o;
            }
        }
    }
}

// ---------------- per-channel sums for BN ----------------
__global__ void k_stats() {
    __shared__ float s_sum[8][128];
    __shared__ float s_sq[8][128];
    int lane = threadIdx.x & 31;
    int w = threadIdx.x >> 5;
    float4 sum = make_float4(0.f, 0.f, 0.f, 0.f);
    float4 sq  = make_float4(0.f, 0.f, 0.f, 0.f);
    for (int r = blockIdx.x * 8 + w; r < N_NODES; r += gridDim.x * 8) {
        float4 v = *reinterpret_cast<const float4*>(g_h + (size_t)r * F + lane * 4);
        sum.x += v.x; sum.y += v.y; sum.z += v.z; sum.w += v.w;
        sq.x += v.x * v.x; sq.y += v.y * v.y; sq.z += v.z * v.z; sq.w += v.w * v.w;
    }
    *reinterpret_cast<float4*>(&s_sum[w][lane * 4]) = sum;
    *reinterpret_cast<float4*>(&s_sq[w][lane * 4])  = sq;
    __syncthreads();
    if (w < 4) {
        int c = w * 32 + lane;
        float ts = 0.f, tq = 0.f;
#pragma unroll
        for (int i = 0; i < 8; i++) { ts += s_sum[i][c]; tq += s_sq[i][c]; }
        atomicAdd(&g_colsum[c], ts);
        atomicAdd(&g_colsq[c], tq);
    }
}

// ---------------- fold mean/var into scale/shift ----------------
__global__ void k_meanvar(const float* __restrict__ gamma, const float* __restrict__ beta) {
    int c = threadIdx.x;
    float mean = g_colsum[c] / (float)N_NODES;
    float var = g_colsq[c] / (float)N_NODES - mean * mean;
    float sc = gamma[c] * rsqrtf(var + BN_EPS);
    g_scale[c] = sc;
    g_shift[c] = beta[c] - mean * sc;
}

// ---------------- BN apply + RReLU in place; also zero agg2 ----------------
__global__ void k_bnrelu() {
    size_t total = (size_t)N_NODES * F / 4;
    float4* h4 = reinterpret_cast<float4*>(g_h);
    float4* a2 = reinterpret_cast<float4*>(&g_agg[1][0]);
    float4 z = make_float4(0.f, 0.f, 0.f, 0.f);
    for (size_t i = (size_t)blockIdx.x * blockDim.x + threadIdx.x; i < total;
         i += (size_t)gridDim.x * blockDim.x) {
        int cb = ((int)(i & 31)) * 4;
        float4 v = h4[i];
        v.x = v.x * g_scale[cb + 0] + g_shift[cb + 0];
        v.y = v.y * g_scale[cb + 1] + g_shift[cb + 1];
        v.z = v.z * g_scale[cb + 2] + g_shift[cb + 2];
        v.w = v.w * g_scale[cb + 3] + g_shift[cb + 3];
        v.x = v.x >= 0.f ? v.x : v.x * RRELU_SLOPE;
        v.y = v.y >= 0.f ? v.y : v.y * RRELU_SLOPE;
        v.z = v.z >= 0.f ? v.z : v.z * RRELU_SLOPE;
        v.w = v.w >= 0.f ? v.w : v.w * RRELU_SLOPE;
        h4[i] = v;
        a2[i] = z;
    }
}

// ---------------- launch ----------------
extern "C" void kernel_launch(void* const* d_in, const int* in_sizes, int n_in,
                              void* d_out, int out_size) {
    const float* x      = (const float*)d_in[0];
    const int*   ei     = (const int*)d_in[1];
    const float* ew     = (const float*)d_in[2];
    const float* W1rel  = (const float*)d_in[3];
    const float* b1     = (const float*)d_in[4];
    const float* W1root = (const float*)d_in[5];
    const float* gamma  = (const float*)d_in[6];
    const float* beta   = (const float*)d_in[7];
    const float* W2rel  = (const float*)d_in[8];
    const float* b2     = (const float*)d_in[9];
    const float* W2root = (const float*)d_in[10];
    float* out = (float*)d_out;

    const int GEMM_BLOCKS = (N_NODES + 127) / 128;          // 391
    const int SCAT_BLOCKS = (N_EDGES * 32 + 255) / 256;     // 100000

    k_init<<<1024, 256>>>();
    k_scatter<<<SCAT_BLOCKS, 256>>>(0, x, ei, ew);
    k_gemm_mma<<<GEMM_BLOCKS, 256>>>(0, x, W1rel, W1root, b1, out);   // -> g_h
    k_stats<<<128, 256>>>();
    k_meanvar<<<1, 128>>>(gamma, beta);
    k_bnrelu<<<2048, 256>>>();                                         // + zero agg2
    k_scatter<<<SCAT_BLOCKS, 256>>>(1, x, ei, ew);
    k_gemm_mma<<<GEMM_BLOCKS, 256>>>(1, x, W2rel, W2root, b2, out);   // -> d_out
}

// round 11
// speedup vs baseline: 1.7020x; 1.0239x over previous
#include <cuda_runtime.h>
#include <math.h>
#include <cstdint>

#define N_NODES 50000
#define N_EDGES 800000
#define F 128
#define BN_EPS 1e-5f
#define RRELU_SLOPE 0.2291666666666667f  // (1/8 + 1/3)/2 = 11/48

// ---------------- scratch (device globals: no allocation allowed) ----------------
__device__ float g_agg[2][(size_t)N_NODES * F];   // agg1, agg2
__device__ float g_h[(size_t)N_NODES * F];        // raw conv1 output (pre-BN)
__device__ float g_colsum[F];
__device__ float g_colsq[F];
__device__ float g_scale[F];
__device__ float g_shift[F];

__device__ __forceinline__ uint32_t cvt_tf32(float f) {
    uint32_t u;
    asm("cvt.rna.tf32.f32 %0, %1;" : "=r"(u) : "f"(f));
    return u;
}

// ---------------- init: zero agg1+agg2 + stats accumulators ----------------
__global__ void k_init() {
    size_t i = (size_t)blockIdx.x * blockDim.x + threadIdx.x;
    size_t total = (size_t)2 * N_NODES * F / 4;
    float4 z = make_float4(0.f, 0.f, 0.f, 0.f);
    float4* a = reinterpret_cast<float4*>(&g_agg[0][0]);
    for (size_t j = i; j < total; j += (size_t)gridDim.x * blockDim.x) a[j] = z;
    if (i < F) { g_colsum[i] = 0.f; g_colsq[i] = 0.f; }
}

// ---------------- scatter: agg[tgt] += w_e * f(feat[src])  (warp per edge) ------------
// layer 1 applies BN scale/shift + RReLU to the gathered h on the fly (g_h stays raw).
__global__ void k_scatter(int layer, const float* __restrict__ x,
                          const int* __restrict__ ei, const float* __restrict__ ew) {
    unsigned gid = blockIdx.x * blockDim.x + threadIdx.x;
    int e = gid >> 5;
    int lane = gid & 31;
    if (e >= N_EDGES) return;
    const float* feat = layer ? g_h : x;
    float* agg = &g_agg[layer][0];

    int s = __ldg(&ei[e]);
    int t = __ldg(&ei[N_EDGES + e]);
    float w = __ldg(&ew[e]);

    float4 v = *reinterpret_cast<const float4*>(feat + (size_t)s * F + lane * 4);
    if (layer) {
        float4 sc = *reinterpret_cast<const float4*>(&g_scale[lane * 4]);
        float4 sh = *reinterpret_cast<const float4*>(&g_shift[lane * 4]);
        v.x = fmaf(v.x, sc.x, sh.x); v.y = fmaf(v.y, sc.y, sh.y);
        v.z = fmaf(v.z, sc.z, sh.z); v.w = fmaf(v.w, sc.w, sh.w);
        v.x = v.x >= 0.f ? v.x : v.x * RRELU_SLOPE;
        v.y = v.y >= 0.f ? v.y : v.y * RRELU_SLOPE;
        v.z = v.z >= 0.f ? v.z : v.z * RRELU_SLOPE;
        v.w = v.w >= 0.f ? v.w : v.w * RRELU_SLOPE;
    }
    float4 r = make_float4(v.x * w, v.y * w, v.z * w, v.w * w);
    float* dst = agg + (size_t)t * F + lane * 4;
    asm volatile("red.global.add.v4.f32 [%0], {%1,%2,%3,%4};"
                 :: "l"(dst), "f"(r.x), "f"(r.y), "f"(r.z), "f"(r.w) : "memory");
}

// ---------------- mma.sync tf32 fused GEMM: C = agg@Wrel^T + f(A1)@Wroot^T + bias ------
// Block: 128 rows x 128 out-cols, 256 threads (8 warps), warp tile 64x32 (4x4 m16n8k8).
// layer 0: epilogue also accumulates per-column sum/sumsq into g_colsum/g_colsq.
// layer 1: A1 (= raw g_h) gets BN scale/shift + RReLU applied during staging.
__global__ void __launch_bounds__(256, 2)
k_gemm_mma(int layer, const float* __restrict__ x,
           const float* __restrict__ Wrel, const float* __restrict__ Wroot,
           const float* __restrict__ bias, float* __restrict__ out) {
    __shared__ uint32_t As[128][36];
    __shared__ uint32_t Bs[128][36];
    __shared__ float s_cs[8][32];
    __shared__ float s_cq[8][32];

    const float* A0 = &g_agg[layer][0];
    const float* A1 = layer ? g_h : x;
    float* C = layer ? out : g_h;

    int tid = threadIdx.x;
    int lane = tid & 31, wid = tid >> 5;
    int row0 = blockIdx.x * 128;
    int mbase = (wid & 1) * 64;     // warp M offset
    int nbase = (wid >> 1) * 32;    // warp N offset
    int grp = lane >> 2;            // 0..7
    int tig = lane & 3;             // 0..3

    float acc[4][4][4];             // [mt][nt][c0..c3]
#pragma unroll
    for (int mt = 0; mt < 4; mt++)
#pragma unroll
        for (int nt = 0; nt < 4; nt++)
#pragma unroll
            for (int q = 0; q < 4; q++) acc[mt][nt][q] = 0.f;

#pragma unroll 1
    for (int t = 0; t < 8; t++) {
        const float* Asrc = (t < 4) ? A0 : A1;
        const float* Bsrc = (t < 4) ? Wrel : Wroot;
        int koff = (t & 3) * 32;
        int bn_stage = (layer != 0) && (t >= 4);

        // stage A tile: 128 rows x 32 k = 1024 float4, 4 per thread
#pragma unroll
        for (int j = 0; j < 4; j++) {
            int i = tid + j * 256;
            int r = i >> 3;                 // 8 float4 per row
            int k4 = (i & 7) << 2;
            float4 v = make_float4(0.f, 0.f, 0.f, 0.f);
            if (row0 + r < N_NODES)
                v = *reinterpret_cast<const float4*>(Asrc + (size_t)(row0 + r) * F + koff + k4);
            if (bn_stage) {
                float4 sc = *reinterpret_cast<const float4*>(&g_scale[koff + k4]);
                float4 sh = *reinterpret_cast<const float4*>(&g_shift[koff + k4]);
                v.x = fmaf(v.x, sc.x, sh.x); v.y = fmaf(v.y, sc.y, sh.y);
                v.z = fmaf(v.z, sc.z, sh.z); v.w = fmaf(v.w, sc.w, sh.w);
                v.x = v.x >= 0.f ? v.x : v.x * RRELU_SLOPE;
                v.y = v.y >= 0.f ? v.y : v.y * RRELU_SLOPE;
                v.z = v.z >= 0.f ? v.z : v.z * RRELU_SLOPE;
                v.w = v.w >= 0.f ? v.w : v.w * RRELU_SLOPE;
            }
            uint4 u = make_uint4(cvt_tf32(v.x), cvt_tf32(v.y), cvt_tf32(v.z), cvt_tf32(v.w));
            *reinterpret_cast<uint4*>(&As[r][k4]) = u;
        }
        // stage B tile: W[n][k] row-major consumed directly
#pragma unroll
        for (int j = 0; j < 4; j++) {
            int i = tid + j * 256;
            int r = i >> 3;
            int k4 = (i & 7) << 2;
            float4 v = *reinterpret_cast<const float4*>(Bsrc + (size_t)r * F + koff + k4);
            uint4 u = make_uint4(cvt_tf32(v.x), cvt_tf32(v.y), cvt_tf32(v.z), cvt_tf32(v.w));
            *reinterpret_cast<uint4*>(&Bs[r][k4]) = u;
        }
        __syncthreads();

#pragma unroll
        for (int ks = 0; ks < 4; ks++) {
            int k0 = ks * 8;
            uint32_t a[4][4], b[4][2];
#pragma unroll
            for (int mt = 0; mt < 4; mt++) {
                int r = mbase + mt * 16 + grp;
                a[mt][0] = As[r][k0 + tig];
                a[mt][1] = As[r + 8][k0 + tig];
                a[mt][2] = As[r][k0 + tig + 4];
                a[mt][3] = As[r + 8][k0 + tig + 4];
            }
#pragma unroll
            for (int nt = 0; nt < 4; nt++) {
                int n = nbase + nt * 8 + grp;
                b[nt][0] = Bs[n][k0 + tig];
                b[nt][1] = Bs[n][k0 + tig + 4];
            }
#pragma unroll
            for (int mt = 0; mt < 4; mt++)
#pragma unroll
                for (int nt = 0; nt < 4; nt++)
                    asm volatile(
                        "mma.sync.aligned.m16n8k8.row.col.f32.tf32.tf32.f32 "
                        "{%0,%1,%2,%3}, {%4,%5,%6,%7}, {%8,%9}, {%0,%1,%2,%3};"
                        : "+f"(acc[mt][nt][0]), "+f"(acc[mt][nt][1]),
                          "+f"(acc[mt][nt][2]), "+f"(acc[mt][nt][3])
                        : "r"(a[mt][0]), "r"(a[mt][1]), "r"(a[mt][2]), "r"(a[mt][3]),
                          "r"(b[nt][0]), "r"(b[nt][1]));
        }
        __syncthreads();
    }

    // epilogue: + bias, store; layer 0 also accumulates BN column stats
    float csum[4][2], csq[4][2];
#pragma unroll
    for (int nt = 0; nt < 4; nt++) {
        csum[nt][0] = csum[nt][1] = 0.f;
        csq[nt][0] = csq[nt][1] = 0.f;
    }

#pragma unroll
    for (int nt = 0; nt < 4; nt++) {
        int c = nbase + nt * 8 + tig * 2;
        float b0 = __ldg(&bias[c]);
        float b1 = __ldg(&bias[c + 1]);
#pragma unroll
        for (int mt = 0; mt < 4; mt++) {
            int r0 = row0 + mbase + mt * 16 + grp;
            int r1 = r0 + 8;
            if (r0 < N_NODES) {
                float v0 = acc[mt][nt][0] + b0;
                float v1 = acc[mt][nt][1] + b1;
                *reinterpret_cast<float2*>(C + (size_t)r0 * F + c) = make_float2(v0, v1);
                csum[nt][0] += v0; csum[nt][1] += v1;
                csq[nt][0] += v0 * v0; csq[nt][1] += v1 * v1;
            }
            if (r1 < N_NODES) {
                float v0 = acc[mt][nt][2] + b0;
                float v1 = acc[mt][nt][3] + b1;
                *reinterpret_cast<float2*>(C + (size_t)r1 * F + c) = make_float2(v0, v1);
                csum[nt][0] += v0; csum[nt][1] += v1;
                csq[nt][0] += v0 * v0; csq[nt][1] += v1 * v1;
            }
        }
    }

    if (layer == 0) {
        // reduce over grp lanes (same tig, 8 grp values) via shfl
#pragma unroll
        for (int nt = 0; nt < 4; nt++)
#pragma unroll
            for (int q = 0; q < 2; q++) {
#pragma unroll
                for (int m = 4; m <= 16; m <<= 1) {
                    csum[nt][q] += __shfl_xor_sync(0xFFFFFFFFu, csum[nt][q], m);
                    csq[nt][q]  += __shfl_xor_sync(0xFFFFFFFFu, csq[nt][q], m);
                }
            }
        if (grp == 0) {   // lanes 0..3
#pragma unroll
            for (int nt = 0; nt < 4; nt++) {
                int cl = nt * 8 + tig * 2;
                s_cs[wid][cl] = csum[nt][0]; s_cs[wid][cl + 1] = csum[nt][1];
                s_cq[wid][cl] = csq[nt][0];  s_cq[wid][cl + 1] = csq[nt][1];
            }
        }
        __syncthreads();
        if (tid < 128) {
            int w0 = (tid >> 5) * 2;       // warps sharing this 32-col group
            int cl = tid & 31;
            float ts = s_cs[w0][cl] + s_cs[w0 + 1][cl];
            float tq = s_cq[w0][cl] + s_cq[w0 + 1][cl];
            atomicAdd(&g_colsum[tid], ts);
            atomicAdd(&g_colsq[tid], tq);
        }
    }
}

// ---------------- fold mean/var into scale/shift ----------------
__global__ void k_meanvar(const float* __restrict__ gamma, const float* __restrict__ beta) {
    int c = threadIdx.x;
    float mean = g_colsum[c] / (float)N_NODES;
    float var = g_colsq[c] / (float)N_NODES - mean * mean;
    float sc = gamma[c] * rsqrtf(var + BN_EPS);
    g_scale[c] = sc;
    g_shift[c] = beta[c] - mean * sc;
}

// ---------------- launch ----------------
extern "C" void kernel_launch(void* const* d_in, const int* in_sizes, int n_in,
                              void* d_out, int out_size) {
    const float* x      = (const float*)d_in[0];
    const int*   ei     = (const int*)d_in[1];
    const float* ew     = (const float*)d_in[2];
    const float* W1rel  = (const float*)d_in[3];
    const float* b1     = (const float*)d_in[4];
    const float* W1root = (const float*)d_in[5];
    const float* gamma  = (const float*)d_in[6];
    const float* beta   = (const float*)d_in[7];
    const float* W2rel  = (const float*)d_in[8];
    const float* b2     = (const float*)d_in[9];
    const float* W2root = (const float*)d_in[10];
    float* out = (float*)d_out;

    const int GEMM_BLOCKS = (N_NODES + 127) / 128;          // 391
    const int SCAT_BLOCKS = (N_EDGES * 32 + 255) / 256;     // 100000

    k_init<<<2048, 256>>>();                                           // zero agg1+agg2
    k_scatter<<<SCAT_BLOCKS, 256>>>(0, x, ei, ew);
    k_gemm_mma<<<GEMM_BLOCKS, 256>>>(0, x, W1rel, W1root, b1, out);   // -> g_h (+ stats)
    k_meanvar<<<1, 128>>>(gamma, beta);
    k_scatter<<<SCAT_BLOCKS, 256>>>(1, x, ei, ew);                    // BN+RReLU on gather
    k_gemm_mma<<<GEMM_BLOCKS, 256>>>(1, x, W2rel, W2root, b2, out);   // -> d_out (BN on A1)
}

// round 12
// speedup vs baseline: 2.2630x; 1.3296x over previous
#include <cuda_runtime.h>
#include <math.h>
#include <cstdint>

#define N_NODES 50000
#define N_EDGES 800000
#define F 128
#define BN_EPS 1e-5f
#define RRELU_SLOPE 0.2291666666666667f  // (1/8 + 1/3)/2 = 11/48

// ---------------- scratch (device globals: no allocation allowed) ----------------
__device__ float g_agg[2][(size_t)N_NODES * F];   // agg1, agg2 (written once per row by gather)
__device__ float g_h[(size_t)N_NODES * F];        // raw conv1 output (pre-BN)
__device__ float g_colsum[F];
__device__ float g_colsq[F];
__device__ float g_scale[F];
__device__ float g_shift[F];
// CSR built per call
__device__ unsigned g_deg[N_NODES];               // in-degree counts
__device__ unsigned g_row[N_NODES + 1];           // exclusive prefix (row offsets)
__device__ unsigned g_cursor[N_NODES];            // placement cursors
__device__ float2 g_edge[N_EDGES];                // (src as int bits, weight), grouped by tgt

__device__ __forceinline__ uint32_t cvt_tf32(float f) {
    uint32_t u;
    asm("cvt.rna.tf32.f32 %0, %1;" : "=r"(u) : "f"(f));
    return u;
}

__device__ __forceinline__ float4 bn_act(float4 v, float4 sc, float4 sh) {
    v.x = fmaf(v.x, sc.x, sh.x); v.y = fmaf(v.y, sc.y, sh.y);
    v.z = fmaf(v.z, sc.z, sh.z); v.w = fmaf(v.w, sc.w, sh.w);
    v.x = v.x >= 0.f ? v.x : v.x * RRELU_SLOPE;
    v.y = v.y >= 0.f ? v.y : v.y * RRELU_SLOPE;
    v.z = v.z >= 0.f ? v.z : v.z * RRELU_SLOPE;
    v.w = v.w >= 0.f ? v.w : v.w * RRELU_SLOPE;
    return v;
}

// ---------------- zero degree counts + BN stat accumulators ----------------
__global__ void k_zero() {
    int i = blockIdx.x * blockDim.x + threadIdx.x;
    for (int j = i; j < N_NODES; j += gridDim.x * blockDim.x) g_deg[j] = 0u;
    if (i < F) { g_colsum[i] = 0.f; g_colsq[i] = 0.f; }
}

// ---------------- histogram of targets ----------------
__global__ void k_hist(const int* __restrict__ ei) {
    int e = blockIdx.x * blockDim.x + threadIdx.x;
    if (e < N_EDGES) atomicAdd(&g_deg[__ldg(&ei[N_EDGES + e])], 1u);
}

// ---------------- single-block exclusive scan of degrees -> row offsets + cursors ------
__global__ void k_scan() {
    __shared__ unsigned wsum[32];
    __shared__ unsigned s_carry;
    int tid = threadIdx.x, lane = tid & 31, wid = tid >> 5;
    if (tid == 0) s_carry = 0u;
    __syncthreads();
    for (int base = 0; base < N_NODES; base += 1024) {
        int i = base + tid;
        unsigned v = (i < N_NODES) ? g_deg[i] : 0u;
        unsigned inc = v;
#pragma unroll
        for (int d = 1; d < 32; d <<= 1) {
            unsigned t = __shfl_up_sync(0xFFFFFFFFu, inc, d);
            if (lane >= d) inc += t;
        }
        if (lane == 31) wsum[wid] = inc;
        __syncthreads();
        if (wid == 0) {
            unsigned s = wsum[lane];
#pragma unroll
            for (int d = 1; d < 32; d <<= 1) {
                unsigned t = __shfl_up_sync(0xFFFFFFFFu, s, d);
                if (lane >= d) s += t;
            }
            wsum[lane] = s;
        }
        __syncthreads();
        unsigned carry = s_carry;
        unsigned excl = carry + inc - v + (wid ? wsum[wid - 1] : 0u);
        if (i < N_NODES) { g_row[i] = excl; g_cursor[i] = excl; }
        __syncthreads();                 // all reads of s_carry/wsum done
        if (tid == 1023) s_carry = carry + wsum[31];
        __syncthreads();
    }
    if (threadIdx.x == 0) g_row[N_NODES] = s_carry;   // == N_EDGES
}

// ---------------- permute edges into tgt-grouped slots ----------------
__global__ void k_permute(const int* __restrict__ ei, const float* __restrict__ ew) {
    int e = blockIdx.x * blockDim.x + threadIdx.x;
    if (e >= N_EDGES) return;
    int t = __ldg(&ei[N_EDGES + e]);
    unsigned slot = atomicAdd(&g_cursor[t], 1u);
    g_edge[slot] = make_float2(__int_as_float(__ldg(&ei[e])), __ldg(&ew[e]));
}

// ---------------- gather: agg[n] = sum_{e in row(n)} w_e * f(feat[src_e]) --------------
// Warp per node; lane owns 4 features. Layer 1 applies BN+RReLU to gathered h.
__global__ void __launch_bounds__(256)
k_gather(int layer, const float* __restrict__ x) {
    int node = blockIdx.x * 8 + (threadIdx.x >> 5);
    int lane = threadIdx.x & 31;
    if (node >= N_NODES) return;
    const float* feat = layer ? g_h : x;

    float4 sc, sh;
    if (layer) {
        sc = *reinterpret_cast<const float4*>(&g_scale[lane * 4]);
        sh = *reinterpret_cast<const float4*>(&g_shift[lane * 4]);
    }

    int e0 = g_row[node], e1 = g_row[node + 1];
    float4 acc = make_float4(0.f, 0.f, 0.f, 0.f);

    int e = e0;
    for (; e + 4 <= e1; e += 4) {
        float2 d0 = __ldg(&g_edge[e]);
        float2 d1 = __ldg(&g_edge[e + 1]);
        float2 d2 = __ldg(&g_edge[e + 2]);
        float2 d3 = __ldg(&g_edge[e + 3]);
        const float4* p0 = reinterpret_cast<const float4*>(feat + (size_t)__float_as_int(d0.x) * F) + lane;
        const float4* p1 = reinterpret_cast<const float4*>(feat + (size_t)__float_as_int(d1.x) * F) + lane;
        const float4* p2 = reinterpret_cast<const float4*>(feat + (size_t)__float_as_int(d2.x) * F) + lane;
        const float4* p3 = reinterpret_cast<const float4*>(feat + (size_t)__float_as_int(d3.x) * F) + lane;
        float4 v0 = __ldg(p0), v1 = __ldg(p1), v2 = __ldg(p2), v3 = __ldg(p3);
        if (layer) { v0 = bn_act(v0, sc, sh); v1 = bn_act(v1, sc, sh);
                     v2 = bn_act(v2, sc, sh); v3 = bn_act(v3, sc, sh); }
        acc.x = fmaf(v0.x, d0.y, acc.x); acc.y = fmaf(v0.y, d0.y, acc.y);
        acc.z = fmaf(v0.z, d0.y, acc.z); acc.w = fmaf(v0.w, d0.y, acc.w);
        acc.x = fmaf(v1.x, d1.y, acc.x); acc.y = fmaf(v1.y, d1.y, acc.y);
        acc.z = fmaf(v1.z, d1.y, acc.z); acc.w = fmaf(v1.w, d1.y, acc.w);
        acc.x = fmaf(v2.x, d2.y, acc.x); acc.y = fmaf(v2.y, d2.y, acc.y);
        acc.z = fmaf(v2.z, d2.y, acc.z); acc.w = fmaf(v2.w, d2.y, acc.w);
        acc.x = fmaf(v3.x, d3.y, acc.x); acc.y = fmaf(v3.y, d3.y, acc.y);
        acc.z = fmaf(v3.z, d3.y, acc.z); acc.w = fmaf(v3.w, d3.y, acc.w);
    }
    for (; e < e1; e++) {
        float2 d0 = __ldg(&g_edge[e]);
        float4 v0 = __ldg(reinterpret_cast<const float4*>(feat + (size_t)__float_as_int(d0.x) * F) + lane);
        if (layer) v0 = bn_act(v0, sc, sh);
        acc.x = fmaf(v0.x, d0.y, acc.x); acc.y = fmaf(v0.y, d0.y, acc.y);
        acc.z = fmaf(v0.z, d0.y, acc.z); acc.w = fmaf(v0.w, d0.y, acc.w);
    }
    *reinterpret_cast<float4*>(&g_agg[layer][(size_t)node * F + lane * 4]) = acc;
}

// ---------------- mma.sync tf32 fused GEMM: C = agg@Wrel^T + f(A1)@Wroot^T + bias ------
__global__ void __launch_bounds__(256, 2)
k_gemm_mma(int layer, const float* __restrict__ x,
           const float* __restrict__ Wrel, const float* __restrict__ Wroot,
           const float* __restrict__ bias, float* __restrict__ out) {
    __shared__ uint32_t As[128][36];
    __shared__ uint32_t Bs[128][36];
    __shared__ float s_cs[8][32];
    __shared__ float s_cq[8][32];

    const float* A0 = &g_agg[layer][0];
    const float* A1 = layer ? g_h : x;
    float* C = layer ? out : g_h;

    int tid = threadIdx.x;
    int lane = tid & 31, wid = tid >> 5;
    int row0 = blockIdx.x * 128;
    int mbase = (wid & 1) * 64;
    int nbase = (wid >> 1) * 32;
    int grp = lane >> 2;
    int tig = lane & 3;

    float acc[4][4][4];
#pragma unroll
    for (int mt = 0; mt < 4; mt++)
#pragma unroll
        for (int nt = 0; nt < 4; nt++)
#pragma unroll
            for (int q = 0; q < 4; q++) acc[mt][nt][q] = 0.f;

#pragma unroll 1
    for (int t = 0; t < 8; t++) {
        const float* Asrc = (t < 4) ? A0 : A1;
        const float* Bsrc = (t < 4) ? Wrel : Wroot;
        int koff = (t & 3) * 32;
        int bn_stage = (layer != 0) && (t >= 4);

#pragma unroll
        for (int j = 0; j < 4; j++) {
            int i = tid + j * 256;
            int r = i >> 3;
            int k4 = (i & 7) << 2;
            float4 v = make_float4(0.f, 0.f, 0.f, 0.f);
            if (row0 + r < N_NODES)
                v = *reinterpret_cast<const float4*>(Asrc + (size_t)(row0 + r) * F + koff + k4);
            if (bn_stage) {
                float4 sc = *reinterpret_cast<const float4*>(&g_scale[koff + k4]);
                float4 sh = *reinterpret_cast<const float4*>(&g_shift[koff + k4]);
                v = bn_act(v, sc, sh);
            }
            uint4 u = make_uint4(cvt_tf32(v.x), cvt_tf32(v.y), cvt_tf32(v.z), cvt_tf32(v.w));
            *reinterpret_cast<uint4*>(&As[r][k4]) = u;
        }
#pragma unroll
        for (int j = 0; j < 4; j++) {
            int i = tid + j * 256;
            int r = i >> 3;
            int k4 = (i & 7) << 2;
            float4 v = *reinterpret_cast<const float4*>(Bsrc + (size_t)r * F + koff + k4);
            uint4 u = make_uint4(cvt_tf32(v.x), cvt_tf32(v.y), cvt_tf32(v.z), cvt_tf32(v.w));
            *reinterpret_cast<uint4*>(&Bs[r][k4]) = u;
        }
        __syncthreads();

#pragma unroll
        for (int ks = 0; ks < 4; ks++) {
            int k0 = ks * 8;
            uint32_t a[4][4], b[4][2];
#pragma unroll
            for (int mt = 0; mt < 4; mt++) {
                int r = mbase + mt * 16 + grp;
                a[mt][0] = As[r][k0 + tig];
                a[mt][1] = As[r + 8][k0 + tig];
                a[mt][2] = As[r][k0 + tig + 4];
                a[mt][3] = As[r + 8][k0 + tig + 4];
            }
#pragma unroll
            for (int nt = 0; nt < 4; nt++) {
                int n = nbase + nt * 8 + grp;
                b[nt][0] = Bs[n][k0 + tig];
                b[nt][1] = Bs[n][k0 + tig + 4];
            }
#pragma unroll
            for (int mt = 0; mt < 4; mt++)
#pragma unroll
                for (int nt = 0; nt < 4; nt++)
                    asm volatile(
                        "mma.sync.aligned.m16n8k8.row.col.f32.tf32.tf32.f32 "
                        "{%0,%1,%2,%3}, {%4,%5,%6,%7}, {%8,%9}, {%0,%1,%2,%3};"
                        : "+f"(acc[mt][nt][0]), "+f"(acc[mt][nt][1]),
                          "+f"(acc[mt][nt][2]), "+f"(acc[mt][nt][3])
                        : "r"(a[mt][0]), "r"(a[mt][1]), "r"(a[mt][2]), "r"(a[mt][3]),
                          "r"(b[nt][0]), "r"(b[nt][1]));
        }
        __syncthreads();
    }

    float csum[4][2], csq[4][2];
#pragma unroll
    for (int nt = 0; nt < 4; nt++) {
        csum[nt][0] = csum[nt][1] = 0.f;
        csq[nt][0] = csq[nt][1] = 0.f;
    }

#pragma unroll
    for (int nt = 0; nt < 4; nt++) {
        int c = nbase + nt * 8 + tig * 2;
        float b0 = __ldg(&bias[c]);
        float b1 = __ldg(&bias[c + 1]);
#pragma unroll
        for (int mt = 0; mt < 4; mt++) {
            int r0 = row0 + mbase + mt * 16 + grp;
            int r1 = r0 + 8;
            if (r0 < N_NODES) {
                float v0 = acc[mt][nt][0] + b0;
                float v1 = acc[mt][nt][1] + b1;
                *reinterpret_cast<float2*>(C + (size_t)r0 * F + c) = make_float2(v0, v1);
                csum[nt][0] += v0; csum[nt][1] += v1;
                csq[nt][0] += v0 * v0; csq[nt][1] += v1 * v1;
            }
            if (r1 < N_NODES) {
                float v0 = acc[mt][nt][2] + b0;
                float v1 = acc[mt][nt][3] + b1;
                *reinterpret_cast<float2*>(C + (size_t)r1 * F + c) = make_float2(v0, v1);
                csum[nt][0] += v0; csum[nt][1] += v1;
                csq[nt][0] += v0 * v0; csq[nt][1] += v1 * v1;
            }
        }
    }

    if (layer == 0) {
#pragma unroll
        for (int nt = 0; nt < 4; nt++)
#pragma unroll
            for (int q = 0; q < 2; q++) {
#pragma unroll
                for (int m = 4; m <= 16; m <<= 1) {
                    csum[nt][q] += __shfl_xor_sync(0xFFFFFFFFu, csum[nt][q], m);
                    csq[nt][q]  += __shfl_xor_sync(0xFFFFFFFFu, csq[nt][q], m);
                }
            }
        if (grp == 0) {
#pragma unroll
            for (int nt = 0; nt < 4; nt++) {
                int cl = nt * 8 + tig * 2;
                s_cs[wid][cl] = csum[nt][0]; s_cs[wid][cl + 1] = csum[nt][1];
                s_cq[wid][cl] = csq[nt][0];  s_cq[wid][cl + 1] = csq[nt][1];
            }
        }
        __syncthreads();
        if (tid < 128) {
            int w0 = (tid >> 5) * 2;
            int cl = tid & 31;
            atomicAdd(&g_colsum[tid], s_cs[w0][cl] + s_cs[w0 + 1][cl]);
            atomicAdd(&g_colsq[tid], s_cq[w0][cl] + s_cq[w0 + 1][cl]);
        }
    }
}

// ---------------- fold mean/var into scale/shift ----------------
__global__ void k_meanvar(const float* __restrict__ gamma, const float* __restrict__ beta) {
    int c = threadIdx.x;
    float mean = g_colsum[c] / (float)N_NODES;
    float var = g_colsq[c] / (float)N_NODES - mean * mean;
    float sc = gamma[c] * rsqrtf(var + BN_EPS);
    g_scale[c] = sc;
    g_shift[c] = beta[c] - mean * sc;
}

// ---------------- launch ----------------
extern "C" void kernel_launch(void* const* d_in, const int* in_sizes, int n_in,
                              void* d_out, int out_size) {
    const float* x      = (const float*)d_in[0];
    const int*   ei     = (const int*)d_in[1];
    const float* ew     = (const float*)d_in[2];
    const float* W1rel  = (const float*)d_in[3];
    const float* b1     = (const float*)d_in[4];
    const float* W1root = (const float*)d_in[5];
    const float* gamma  = (const float*)d_in[6];
    const float* beta   = (const float*)d_in[7];
    const float* W2rel  = (const float*)d_in[8];
    const float* b2     = (const float*)d_in[9];
    const float* W2root = (const float*)d_in[10];
    float* out = (float*)d_out;

    const int GEMM_BLOCKS = (N_NODES + 127) / 128;       // 391
    const int EDGE_BLOCKS = (N_EDGES + 255) / 256;       // 3125
    const int GATH_BLOCKS = (N_NODES + 7) / 8;           // 6250

    k_zero<<<128, 256>>>();
    k_hist<<<EDGE_BLOCKS, 256>>>(ei);
    k_scan<<<1, 1024>>>();
    k_permute<<<EDGE_BLOCKS, 256>>>(ei, ew);
    k_gather<<<GATH_BLOCKS, 256>>>(0, x);                              // -> agg1
    k_gemm_mma<<<GEMM_BLOCKS, 256>>>(0, x, W1rel, W1root, b1, out);    // -> g_h (+ stats)
    k_meanvar<<<1, 128>>>(gamma, beta);
    k_gather<<<GATH_BLOCKS, 256>>>(1, x);                              // -> agg2 (BN+RReLU)
    k_gemm_mma<<<GEMM_BLOCKS, 256>>>(1, x, W2rel, W2root, b2, out);    // -> d_out
}